// round 2
// baseline (speedup 1.0000x reference)
#include <cuda_runtime.h>
#include <mma.h>
#include <math.h>

using namespace nvcuda;

// Problem constants (fixed shapes)
#define T_TOK 2048
#define DIM   2048
#define NE    16
#define NI    1024
#define SIH   2048
#define TOPK  4
#define CAP   2048   // per-expert token capacity (worst case)

// ---------------- scratch (device globals; no allocation allowed) ----------------
__device__ int   d_top_idx[T_TOK * TOPK];
__device__ float d_top_w[T_TOK * TOPK];
__device__ int   d_pos[T_TOK * TOPK];     // position of (token,slot) within its expert's list
__device__ int   d_counts[NE];
__device__ int   d_tok[NE * CAP];
// gu scratch: shared gu (2048x4096), expert gu (16x2048x2048), and expert y (16x2048x2048)
__device__ float d_gu[(size_t)NE * CAP * 2048];
// act scratch: shared act (2048x2048) and expert act (16x2048x1024)
__device__ float d_act[(size_t)NE * CAP * NI];

__device__ __forceinline__ float silu_f(float v) {
    return v / (1.0f + expf(-v));
}

// ---------------- router ----------------
__global__ void router_kernel(const float* __restrict__ x,
                              const float* __restrict__ gw,
                              const float* __restrict__ gb,
                              int* __restrict__ tidx, float* __restrict__ tw) {
    const int t = blockIdx.x;
    const int tid = threadIdx.x;
    const float* xr = x + (size_t)t * DIM;
    float acc[NE];
#pragma unroll
    for (int e = 0; e < NE; ++e) acc[e] = 0.0f;
    for (int d = tid; d < DIM; d += 128) {
        float xv = xr[d];
#pragma unroll
        for (int e = 0; e < NE; ++e) acc[e] += xv * gw[e * DIM + d];
    }
    __shared__ float red[NE][128];
#pragma unroll
    for (int e = 0; e < NE; ++e) red[e][tid] = acc[e];
    __syncthreads();
    for (int s = 64; s > 0; s >>= 1) {
        if (tid < s) {
#pragma unroll
            for (int e = 0; e < NE; ++e) red[e][tid] += red[e][tid + s];
        }
        __syncthreads();
    }
    if (tid == 0) {
        float logit[NE], p[NE];
        float mx = -1e30f;
#pragma unroll
        for (int e = 0; e < NE; ++e) { logit[e] = red[e][0]; mx = fmaxf(mx, logit[e]); }
        float sum = 0.0f;
#pragma unroll
        for (int e = 0; e < NE; ++e) { p[e] = expf(logit[e] - mx); sum += p[e]; }
        float inv = 1.0f / sum;
#pragma unroll
        for (int e = 0; e < NE; ++e) p[e] *= inv;
        float bmin = gb[0];
#pragma unroll
        for (int e = 1; e < NE; ++e) bmin = fminf(bmin, gb[e]);
        float biased[NE];
#pragma unroll
        for (int e = 0; e < NE; ++e) biased[e] = p[e] + (gb[e] - bmin);
        int sel[TOPK];
        float wsum = 0.0f;
#pragma unroll
        for (int k = 0; k < TOPK; ++k) {
            int bi = 0; float bv = -1e30f;
#pragma unroll
            for (int e = 0; e < NE; ++e)
                if (biased[e] > bv) { bv = biased[e]; bi = e; }
            sel[k] = bi;
            wsum += p[bi];
            biased[bi] = -1e30f;
        }
        float invw = 1.0f / wsum;
#pragma unroll
        for (int k = 0; k < TOPK; ++k) {
            tidx[t * TOPK + k] = sel[k];
            tw[t * TOPK + k] = p[sel[k]] * invw;
        }
    }
}

// ---------------- deterministic routing build + inverse map ----------------
__global__ void routing_build(const int* __restrict__ tidx,
                              int* __restrict__ tok,
                              int* __restrict__ posOut,
                              int* __restrict__ counts) {
    const int e = blockIdx.x;
    const int tid = threadIdx.x;
    const int lane = tid & 31, wid = tid >> 5;
    __shared__ int wcnts[8];
    int cnt = 0;
    for (int base = 0; base < T_TOK * TOPK; base += 256) {
        int i = base + tid;
        bool m = (tidx[i] == e);
        unsigned ball = __ballot_sync(0xffffffffu, m);
        if (lane == 0) wcnts[wid] = __popc(ball);
        __syncthreads();
        int woff = 0, tot = 0;
#pragma unroll
        for (int w = 0; w < 8; ++w) { int c = wcnts[w]; if (w < wid) woff += c; tot += c; }
        if (m) {
            int pos = cnt + woff + __popc(ball & ((1u << lane) - 1u));
            tok[e * CAP + pos] = i >> 2;   // token id
            posOut[i] = pos;               // inverse map
        }
        cnt += tot;
        __syncthreads();
    }
    if (tid == 0) counts[e] = cnt;
}

// ---------------- swiglu elementwise ----------------
__global__ void swiglu_shared(const float* __restrict__ gu, float* __restrict__ act) {
    size_t gi = (size_t)blockIdx.x * 256 + threadIdx.x;   // over 2048*2048
    int t = (int)(gi >> 11);
    int j = (int)(gi & 2047);
    const float* row = gu + (size_t)t * (2 * SIH);
    float g = row[j];
    float u = row[SIH + j];
    act[gi] = silu_f(g) * u;
}

__global__ void swiglu_expert(const float* __restrict__ gu, float* __restrict__ act,
                              const int* __restrict__ counts) {
    size_t gi = (size_t)blockIdx.x * 256 + threadIdx.x;   // over NE*CAP*NI
    int e = (int)(gi >> 21);
    int rem = (int)(gi & ((1u << 21) - 1u));
    int r = rem >> 10;
    int j = rem & (NI - 1);
    if (r >= counts[e]) return;
    const float* row = gu + ((size_t)e * CAP + r) * (2 * NI);
    float g = row[j];
    float u = row[NI + j];
    act[gi] = silu_f(g) * u;
}

// ---------------- final combine: out += sum_k w_k * y[e_k][pos_k] ----------------
__global__ void combine_kernel(const float* __restrict__ y,
                               const int* __restrict__ tidx,
                               const int* __restrict__ posArr,
                               const float* __restrict__ tw,
                               float* __restrict__ out) {
    const int b = blockIdx.x;
    const int t = b >> 1;
    const int half = b & 1;
    const int j = half * 1024 + threadIdx.x * 4;
    float4 o = *(const float4*)(out + (size_t)t * DIM + j);
#pragma unroll
    for (int k = 0; k < TOPK; ++k) {
        int e = tidx[t * TOPK + k];
        int p = posArr[t * TOPK + k];
        float w = tw[t * TOPK + k];
        const float4 yv = *(const float4*)(y + ((size_t)e * CAP + p) * DIM + j);
        o.x += w * yv.x; o.y += w * yv.y; o.z += w * yv.z; o.w += w * yv.w;
    }
    *(float4*)(out + (size_t)t * DIM + j) = o;
}

// ---------------- tf32 WMMA GEMM: 128x128 tile, BK=16, 8 warps, dbl-buffered ----
// A row-major [rows, K] (optionally gathered rows), B row-major [K, N], C row-major.
// Expert variants padded to CAP rows in C scratch, so no store masking needed.
template <bool GATHER>
__global__ __launch_bounds__(256)
void tgemm_kernel(const float* __restrict__ Abase, long long sAe,
                  const float* __restrict__ Bbase, long long sBe,
                  float* __restrict__ Cbase, long long sCe,
                  const int* __restrict__ counts, int Mfull,
                  int N, int K,
                  const int* __restrict__ tokBase) {
    const int e = blockIdx.z;
    const int M = counts ? counts[e] : Mfull;
    const int m0 = blockIdx.y * 128;
    if (m0 >= M) return;
    const int n0 = blockIdx.x * 128;

    const float* A = Abase + (size_t)e * sAe;
    const float* B = Bbase + (size_t)e * sBe;
    float* C = Cbase + (size_t)e * sCe;
    const int* tok = GATHER ? (tokBase + e * CAP) : (const int*)0;

    __shared__ float As[2][128][20];   // ldm=20 (mult of 4), padded vs conflicts
    __shared__ float Bs[2][16][136];   // ldm=136

    const int tid = threadIdx.x;

    // A loads: 2 float4 per thread. q=0 -> rows 0..63, q=1 -> rows 64..127
    const int arow0 = tid >> 2;
    const int acol = (tid & 3) << 2;
    int asrc[2];
#pragma unroll
    for (int q = 0; q < 2; ++q) {
        int ar = m0 + arow0 + q * 64;
        if (GATHER) {
            int idx = (ar < M) ? ar : (M - 1);
            asrc[q] = tok[idx];
        } else {
            asrc[q] = (ar < M) ? ar : (M - 1);
        }
    }
    const float* Ap0 = A + (size_t)asrc[0] * K + acol;
    const float* Ap1 = A + (size_t)asrc[1] * K + acol;

    // B loads: 2 float4 per thread. q=0 -> k rows 0..7, q=1 -> rows 8..15
    const int brow0 = tid >> 5;
    const int bcol = (tid & 31) << 2;
    const float* Bp0 = B + (size_t)brow0 * N + n0 + bcol;
    const float* Bp1 = B + (size_t)(brow0 + 8) * N + n0 + bcol;

    float4 av0 = *(const float4*)(Ap0);
    float4 av1 = *(const float4*)(Ap1);
    float4 bv0 = *(const float4*)(Bp0);
    float4 bv1 = *(const float4*)(Bp1);

#define TF32_CVT4(v) make_float4(wmma::__float_to_tf32(v.x), wmma::__float_to_tf32(v.y), \
                                 wmma::__float_to_tf32(v.z), wmma::__float_to_tf32(v.w))

    {
        float4 c;
        c = TF32_CVT4(av0); *(float4*)&As[0][arow0][acol] = c;
        c = TF32_CVT4(av1); *(float4*)&As[0][arow0 + 64][acol] = c;
        c = TF32_CVT4(bv0); *(float4*)&Bs[0][brow0][bcol] = c;
        c = TF32_CVT4(bv1); *(float4*)&Bs[0][brow0 + 8][bcol] = c;
    }
    __syncthreads();

    const int wid = tid >> 5;
    const int wr = wid & 1;        // 2 warp rows  -> 64 rows each
    const int wc = wid >> 1;       // 4 warp cols  -> 32 cols each

    wmma::fragment<wmma::accumulator, 16, 16, 8, float> cf[4][2];
#pragma unroll
    for (int i = 0; i < 4; ++i)
#pragma unroll
        for (int j = 0; j < 2; ++j) wmma::fill_fragment(cf[i][j], 0.0f);

    const int numT = K >> 4;
    for (int t = 0; t < numT; ++t) {
        const int cur = t & 1;
        if (t + 1 < numT) {
            const size_t koff = (size_t)(t + 1) * 16;
            av0 = *(const float4*)(Ap0 + koff);
            av1 = *(const float4*)(Ap1 + koff);
            bv0 = *(const float4*)(Bp0 + koff * N);
            bv1 = *(const float4*)(Bp1 + koff * N);
        }

#pragma unroll
        for (int kk = 0; kk < 16; kk += 8) {
            wmma::fragment<wmma::matrix_a, 16, 16, 8, wmma::precision::tf32, wmma::row_major> af[4];
            wmma::fragment<wmma::matrix_b, 16, 16, 8, wmma::precision::tf32, wmma::row_major> bf[2];
#pragma unroll
            for (int i = 0; i < 4; ++i)
                wmma::load_matrix_sync(af[i], &As[cur][wr * 64 + i * 16][kk], 20);
#pragma unroll
            for (int j = 0; j < 2; ++j)
                wmma::load_matrix_sync(bf[j], &Bs[cur][kk][wc * 32 + j * 16], 136);
#pragma unroll
            for (int i = 0; i < 4; ++i)
#pragma unroll
                for (int j = 0; j < 2; ++j)
                    wmma::mma_sync(cf[i][j], af[i], bf[j], cf[i][j]);
        }

        if (t + 1 < numT) {
            const int nxt = cur ^ 1;
            float4 c;
            c = TF32_CVT4(av0); *(float4*)&As[nxt][arow0][acol] = c;
            c = TF32_CVT4(av1); *(float4*)&As[nxt][arow0 + 64][acol] = c;
            c = TF32_CVT4(bv0); *(float4*)&Bs[nxt][brow0][bcol] = c;
            c = TF32_CVT4(bv1); *(float4*)&Bs[nxt][brow0 + 8][bcol] = c;
        }
        __syncthreads();
    }

    // Epilogue: plain stores (expert C scratch is CAP-padded; shared shapes exact)
    float* Ct = C + (size_t)(m0 + wr * 64) * N + n0 + wc * 32;
#pragma unroll
    for (int i = 0; i < 4; ++i)
#pragma unroll
        for (int j = 0; j < 2; ++j)
            wmma::store_matrix_sync(Ct + (size_t)i * 16 * N + j * 16, cf[i][j], N,
                                    wmma::mem_row_major);
}

// ---------------- launch ----------------
extern "C" void kernel_launch(void* const* d_in, const int* in_sizes, int n_in,
                              void* d_out, int out_size) {
    const float* x    = (const float*)d_in[0];
    const float* gw   = (const float*)d_in[1];
    const float* gb   = (const float*)d_in[2];
    const float* wgu  = (const float*)d_in[3];   // [E, D, 2I]
    const float* wdn  = (const float*)d_in[4];   // [E, I, D]
    const float* wsgu = (const float*)d_in[5];   // [D, 2*SI]
    const float* wsd  = (const float*)d_in[6];   // [SI, D]
    float* out = (float*)d_out;

    void* p;
    cudaGetSymbolAddress(&p, d_gu);      float* gu  = (float*)p;   // also y scratch
    cudaGetSymbolAddress(&p, d_act);     float* act = (float*)p;
    cudaGetSymbolAddress(&p, d_tok);     int*   tok = (int*)p;
    cudaGetSymbolAddress(&p, d_counts);  int*   cnt = (int*)p;
    cudaGetSymbolAddress(&p, d_top_idx); int*   ti  = (int*)p;
    cudaGetSymbolAddress(&p, d_top_w);   float* tw  = (float*)p;
    cudaGetSymbolAddress(&p, d_pos);     int*   pos = (int*)p;

    // 1) router + routing tables
    router_kernel<<<T_TOK, 128>>>(x, gw, gb, ti, tw);
    routing_build<<<NE, 256>>>(ti, tok, pos, cnt);

    // 2) shared expert: gu = x @ w_shared_gate_up  [2048 x 4096]
    tgemm_kernel<false><<<dim3(2 * SIH / 128, T_TOK / 128, 1), 256>>>(
        x, 0, wsgu, 0, gu, 0, (const int*)0, T_TOK, 2 * SIH, DIM, (const int*)0);
    swiglu_shared<<<(T_TOK * SIH) / 256, 256>>>(gu, act);
    // out = act @ w_shared_down (full store initializes out)
    tgemm_kernel<false><<<dim3(DIM / 128, T_TOK / 128, 1), 256>>>(
        act, 0, wsd, 0, out, 0, (const int*)0, T_TOK, DIM, SIH, (const int*)0);

    // 3) routed experts: gu[e] = gather(x) @ w_gate_up[e]   [count_e x 2048]
    tgemm_kernel<true><<<dim3(2 * NI / 128, CAP / 128, NE), 256>>>(
        x, 0, wgu, (long long)DIM * 2 * NI, gu, (long long)CAP * 2 * NI,
        cnt, 0, 2 * NI, DIM, tok);
    swiglu_expert<<<(NE * CAP * NI) / 256, 256>>>(gu, act, cnt);
    // y[e] = act[e] @ w_down[e]  (dense store into gu scratch, reused as y)
    tgemm_kernel<false><<<dim3(DIM / 128, CAP / 128, NE), 256>>>(
        act, (long long)CAP * NI, wdn, (long long)NI * DIM, gu, (long long)CAP * DIM,
        cnt, 0, DIM, NI, (const int*)0);
    // out += sum_k w_k * y[e_k][pos_k]
    combine_kernel<<<T_TOK * 2, 256>>>(gu, ti, pos, tw, out);
}

// round 10
// speedup vs baseline: 1.5745x; 1.5745x over previous
#include <cuda_runtime.h>
#include <math.h>
#include <stdint.h>

// Problem constants (fixed shapes)
#define T_TOK 2048
#define DIM   2048
#define NE    16
#define NI    1024
#define SIH   2048
#define TOPK  4
#define CAP   2048

// ---------------- scratch (device globals; no allocation allowed) ----------------
__device__ int   d_top_idx[T_TOK * TOPK];
__device__ float d_top_w[T_TOK * TOPK];
__device__ int   d_pos[T_TOK * TOPK];
__device__ int   d_counts[NE];
__device__ int   d_tok[NE * CAP];
__device__ float d_xt[(size_t)T_TOK * DIM];                    // tf32-rounded x
__device__ float d_wgu_t[(size_t)NE * (2 * NI) * DIM];         // [E][2I][D] tf32
__device__ float d_wdn_t[(size_t)NE * DIM * NI];               // [E][D][I]  tf32
__device__ float d_wsgu_t[(size_t)(2 * SIH) * DIM];            // [2SI][D]   tf32
__device__ float d_wsd_t[(size_t)DIM * SIH];                   // [D][SI]    tf32
__device__ float d_gu[(size_t)NE * CAP * 2048];                // fp32 gu / y scratch
__device__ float d_acts[(size_t)T_TOK * SIH];                  // tf32-rounded shared act
__device__ float d_acte[(size_t)NE * CAP * NI];                // tf32-rounded expert act

__device__ __forceinline__ float silu_f(float v) { return v / (1.0f + expf(-v)); }

__device__ __forceinline__ float to_tf32(float a) {
    uint32_t u;
    asm("cvt.rna.tf32.f32 %0, %1;" : "=r"(u) : "f"(a));
    return __uint_as_float(u);
}

__device__ __forceinline__ uint32_t s2u(const void* p) {
    uint32_t a;
    asm("{ .reg .u64 t; cvta.to.shared.u64 t, %1; cvt.u32.u64 %0, t; }" : "=r"(a) : "l"(p));
    return a;
}

#define CP16(sm, gp) asm volatile("cp.async.cg.shared.global [%0], [%1], 16;" :: "r"(sm), "l"(gp))
#define CP_COMMIT()  asm volatile("cp.async.commit_group;" ::: "memory")
#define CP_WAIT1()   asm volatile("cp.async.wait_group 1;" ::: "memory")

#define LDSM4(r, a) \
    asm volatile("ldmatrix.sync.aligned.m8n8.x4.shared.b16 {%0,%1,%2,%3}, [%4];" \
        : "=r"((r)[0]), "=r"((r)[1]), "=r"((r)[2]), "=r"((r)[3]) : "r"(a))

#define MMA_TF32(c, a, b0, b1) \
    asm volatile("mma.sync.aligned.m16n8k8.row.col.f32.tf32.tf32.f32 " \
        "{%0,%1,%2,%3}, {%4,%5,%6,%7}, {%8,%9}, {%0,%1,%2,%3};" \
        : "+f"((c)[0]), "+f"((c)[1]), "+f"((c)[2]), "+f"((c)[3]) \
        : "r"((a)[0]), "r"((a)[1]), "r"((a)[2]), "r"((a)[3]), "r"(b0), "r"(b1))

// ---------------- router ----------------
__global__ void router_kernel(const float* __restrict__ x,
                              const float* __restrict__ gw,
                              const float* __restrict__ gb,
                              int* __restrict__ tidx, float* __restrict__ tw) {
    const int t = blockIdx.x;
    const int tid = threadIdx.x;
    const float* xr = x + (size_t)t * DIM;
    float acc[NE];
#pragma unroll
    for (int e = 0; e < NE; ++e) acc[e] = 0.0f;
    for (int d = tid; d < DIM; d += 128) {
        float xv = xr[d];
#pragma unroll
        for (int e = 0; e < NE; ++e) acc[e] += xv * gw[e * DIM + d];
    }
    __shared__ float red[NE][128];
#pragma unroll
    for (int e = 0; e < NE; ++e) red[e][tid] = acc[e];
    __syncthreads();
    for (int s = 64; s > 0; s >>= 1) {
        if (tid < s) {
#pragma unroll
            for (int e = 0; e < NE; ++e) red[e][tid] += red[e][tid + s];
        }
        __syncthreads();
    }
    if (tid == 0) {
        float logit[NE], p[NE];
        float mx = -1e30f;
#pragma unroll
        for (int e = 0; e < NE; ++e) { logit[e] = red[e][0]; mx = fmaxf(mx, logit[e]); }
        float sum = 0.0f;
#pragma unroll
        for (int e = 0; e < NE; ++e) { p[e] = expf(logit[e] - mx); sum += p[e]; }
        float inv = 1.0f / sum;
#pragma unroll
        for (int e = 0; e < NE; ++e) p[e] *= inv;
        float bmin = gb[0];
#pragma unroll
        for (int e = 1; e < NE; ++e) bmin = fminf(bmin, gb[e]);
        float biased[NE];
#pragma unroll
        for (int e = 0; e < NE; ++e) biased[e] = p[e] + (gb[e] - bmin);
        int sel[TOPK];
        float wsum = 0.0f;
#pragma unroll
        for (int k = 0; k < TOPK; ++k) {
            int bi = 0; float bv = -1e30f;
#pragma unroll
            for (int e = 0; e < NE; ++e)
                if (biased[e] > bv) { bv = biased[e]; bi = e; }
            sel[k] = bi;
            wsum += p[bi];
            biased[bi] = -1e30f;
        }
        float invw = 1.0f / wsum;
#pragma unroll
        for (int k = 0; k < TOPK; ++k) {
            tidx[t * TOPK + k] = sel[k];
            tw[t * TOPK + k] = p[sel[k]] * invw;
        }
    }
}

// ---------------- deterministic routing build + inverse map ----------------
__global__ void routing_build(const int* __restrict__ tidx,
                              int* __restrict__ tok,
                              int* __restrict__ posOut,
                              int* __restrict__ counts) {
    const int e = blockIdx.x;
    const int tid = threadIdx.x;
    const int lane = tid & 31, wid = tid >> 5;
    __shared__ int wcnts[8];
    int cnt = 0;
    for (int base = 0; base < T_TOK * TOPK; base += 256) {
        int i = base + tid;
        bool m = (tidx[i] == e);
        unsigned ball = __ballot_sync(0xffffffffu, m);
        if (lane == 0) wcnts[wid] = __popc(ball);
        __syncthreads();
        int woff = 0, tot = 0;
#pragma unroll
        for (int w = 0; w < 8; ++w) { int c = wcnts[w]; if (w < wid) woff += c; tot += c; }
        if (m) {
            int pos = cnt + woff + __popc(ball & ((1u << lane) - 1u));
            tok[e * CAP + pos] = i >> 2;
            posOut[i] = pos;
        }
        cnt += tot;
        __syncthreads();
    }
    if (tid == 0) counts[e] = cnt;
}

// ---------------- prep: tf32-round x ----------------
__global__ void round_x_kernel(const float* __restrict__ x, float* __restrict__ xt) {
    size_t gi = ((size_t)blockIdx.x * 256 + threadIdx.x) * 4;
    float4 v = *(const float4*)(x + gi);
    v.x = to_tf32(v.x); v.y = to_tf32(v.y); v.z = to_tf32(v.z); v.w = to_tf32(v.w);
    *(float4*)(xt + gi) = v;
}

// ---------------- prep: transpose W[R][C] -> O[C][R] tf32-rounded ----------------
__global__ void transpose_tf32(const float* __restrict__ Wb, long long sWe,
                               float* __restrict__ Ob, long long sOe,
                               int R, int C) {
    const float* W = Wb + (size_t)blockIdx.z * sWe;
    float* O = Ob + (size_t)blockIdx.z * sOe;
    const int r0 = blockIdx.y * 32;
    const int c0 = blockIdx.x * 32;
    __shared__ float s[32][33];
    const int tx = threadIdx.x;   // 32
    const int ty = threadIdx.y;   // 8
#pragma unroll
    for (int i = 0; i < 4; ++i)
        s[ty + 8 * i][tx] = W[(size_t)(r0 + ty + 8 * i) * C + c0 + tx];
    __syncthreads();
#pragma unroll
    for (int i = 0; i < 4; ++i)
        O[(size_t)(c0 + ty + 8 * i) * R + r0 + tx] = to_tf32(s[tx][ty + 8 * i]);
}

// ---------------- swiglu (fp32 in, tf32-rounded fp32 out) ----------------
__global__ void swiglu_shared(const float* __restrict__ gu, float* __restrict__ act) {
    size_t gi = ((size_t)blockIdx.x * 256 + threadIdx.x) * 4;   // over T*SIH
    int t = (int)(gi >> 11);
    int j = (int)(gi & 2047);
    const float* row = gu + (size_t)t * (2 * SIH);
    float4 g = *(const float4*)(row + j);
    float4 u = *(const float4*)(row + SIH + j);
    float4 o;
    o.x = to_tf32(silu_f(g.x) * u.x);
    o.y = to_tf32(silu_f(g.y) * u.y);
    o.z = to_tf32(silu_f(g.z) * u.z);
    o.w = to_tf32(silu_f(g.w) * u.w);
    *(float4*)(act + gi) = o;
}

__global__ void swiglu_expert(const float* __restrict__ gu, float* __restrict__ act,
                              const int* __restrict__ counts) {
    size_t gi = ((size_t)blockIdx.x * 256 + threadIdx.x) * 4;   // over NE*CAP*NI
    int e = (int)(gi >> 21);
    int rem = (int)(gi & ((1u << 21) - 1u));
    int r = rem >> 10;
    int j = rem & (NI - 1);
    if (r >= counts[e]) return;
    const float* row = gu + ((size_t)e * CAP + r) * (2 * NI);
    float4 g = *(const float4*)(row + j);
    float4 u = *(const float4*)(row + NI + j);
    float4 o;
    o.x = to_tf32(silu_f(g.x) * u.x);
    o.y = to_tf32(silu_f(g.y) * u.y);
    o.z = to_tf32(silu_f(g.z) * u.z);
    o.w = to_tf32(silu_f(g.w) * u.w);
    *(float4*)(act + gi) = o;
}

// ---------------- final combine ----------------
__global__ void combine_kernel(const float* __restrict__ y,
                               const int* __restrict__ tidx,
                               const int* __restrict__ posArr,
                               const float* __restrict__ tw,
                               float* __restrict__ out) {
    const int b = blockIdx.x;
    const int t = b >> 1;
    const int half = b & 1;
    const int j = half * 1024 + threadIdx.x * 4;
    float4 o = *(const float4*)(out + (size_t)t * DIM + j);
#pragma unroll
    for (int k = 0; k < TOPK; ++k) {
        int e = tidx[t * TOPK + k];
        int p = posArr[t * TOPK + k];
        float w = tw[t * TOPK + k];
        const float4 yv = *(const float4*)(y + ((size_t)e * CAP + p) * DIM + j);
        o.x += w * yv.x; o.y += w * yv.y; o.z += w * yv.z; o.w += w * yv.w;
    }
    *(float4*)(out + (size_t)t * DIM + j) = o;
}

// ============================================================================
// tf32 mma.sync GEMM: BM=128, BN=128, BK=32, 3-stage cp.async, ldmatrix frags.
// A [rows][K] tf32-f32 (optionally gathered rows), B [N][K] tf32-f32,
// C fp32 [rows][ldc].
// ============================================================================
#define GSMEM_BYTES (3 * 32768)

template <bool GATHER>
__global__ __launch_bounds__(256, 1)
void mma_gemm(const float* __restrict__ Ab, long long sAe, int lda,
              const float* __restrict__ Bb, long long sBe, int ldb,
              float* __restrict__ Cb, long long sCe, int ldc,
              const int* __restrict__ counts, int Mfull, int KT,
              const int* __restrict__ tokBase) {
    const int e = blockIdx.z;
    const int M = counts ? counts[e] : Mfull;
    const int m0 = blockIdx.y * 128;
    if (m0 >= M) return;
    const int n0 = blockIdx.x * 128;

    extern __shared__ char dynsmem[];
    const uint32_t sbase = s2u(dynsmem);

    const float* A = Ab + (size_t)e * sAe;
    const float* B = Bb + (size_t)e * sBe;
    float* C = Cb + (size_t)e * sCe;

    const int tid = threadIdx.x;
    const int lane = tid & 31;
    const int wid = tid >> 5;
    const int wm = wid & 1;        // 2 M-halves of 64
    const int wn = wid >> 1;       // 4 N-quarters of 32

    // ---- cp.async geometry: thread owns one row (tid>>1), half (tid&1) ----
    const int rl = tid >> 1;               // 0..127
    const int halfsel = tid & 1;
    int gr = m0 + rl;
    int grc = (gr < M) ? gr : (M - 1);
    const int src = GATHER ? tokBase[e * CAP + grc] : grc;
    const float* aptr = A + (size_t)src * lda + halfsel * 16;
    const float* bptr = B + (size_t)(n0 + rl) * ldb + halfsel * 16;
    uint32_t sw[4];
#pragma unroll
    for (int j = 0; j < 4; ++j) {
        int kc = halfsel * 4 + j;
        sw[j] = (uint32_t)(((kc ^ (rl & 7)) << 4));
    }
    const uint32_t rowOff = (uint32_t)rl * 128u;

    // ---- ldmatrix geometry ----
    const uint32_t l7 = (uint32_t)(lane & 7);
    const uint32_t abit = (uint32_t)(lane >> 4);          // A: chunk select
    const uint32_t bbit = (uint32_t)((lane >> 3) & 1);    // B: chunk select
    const int ar = (lane & 7) + ((lane >> 3) & 1) * 8;
    const int br = (lane & 7) + (lane >> 4) * 8;
    uint32_t aOff[4], bOff[2];
#pragma unroll
    for (int mt = 0; mt < 4; ++mt)
        aOff[mt] = (uint32_t)((wm * 64 + mt * 16 + ar) * 128);
#pragma unroll
    for (int nt2 = 0; nt2 < 2; ++nt2)
        bOff[nt2] = (uint32_t)((wn * 32 + nt2 * 16 + br) * 128);

    float acc[4][4][4];
#pragma unroll
    for (int i = 0; i < 4; ++i)
#pragma unroll
        for (int j = 0; j < 4; ++j)
#pragma unroll
            for (int q = 0; q < 4; ++q) acc[i][j][q] = 0.0f;

    // ---- stage loader ----
    auto load_stage = [&](int s, int kt) {
        const uint32_t as = sbase + (uint32_t)s * 32768u + rowOff;
        const uint32_t bs = as + 16384u;
        const float* ap = aptr + (size_t)kt * 32;
        const float* bp = bptr + (size_t)kt * 32;
#pragma unroll
        for (int j = 0; j < 4; ++j) {
            CP16(as + sw[j], ap + j * 4);
            CP16(bs + sw[j], bp + j * 4);
        }
    };

    // prologue: stages 0,1
    load_stage(0, 0); CP_COMMIT();
    if (KT > 1) load_stage(1, 1);
    CP_COMMIT();
    CP_WAIT1();
    __syncthreads();

    int cur = 0;
    for (int kt = 0; kt < KT; ++kt) {
        if (kt + 2 < KT) load_stage((kt + 2) % 3, kt + 2);
        CP_COMMIT();

        const uint32_t As0 = sbase + (uint32_t)cur * 32768u;
        const uint32_t Bs0 = As0 + 16384u;
#pragma unroll
        for (int s8 = 0; s8 < 4; ++s8) {
            uint32_t a[4][4];
            uint32_t b[2][4];
            const uint32_t ach = (((uint32_t)(s8 * 2) + abit) ^ l7) << 4;
            const uint32_t bch = (((uint32_t)(s8 * 2) + bbit) ^ l7) << 4;
#pragma unroll
            for (int mt = 0; mt < 4; ++mt) LDSM4(a[mt], As0 + aOff[mt] + ach);
#pragma unroll
            for (int nt2 = 0; nt2 < 2; ++nt2) LDSM4(b[nt2], Bs0 + bOff[nt2] + bch);
#pragma unroll
            for (int mt = 0; mt < 4; ++mt) {
#pragma unroll
                for (int nt = 0; nt < 4; ++nt) {
                    const uint32_t b0 = b[nt >> 1][(nt & 1) * 2 + 0];
                    const uint32_t b1 = b[nt >> 1][(nt & 1) * 2 + 1];
                    MMA_TF32(acc[mt][nt], a[mt], b0, b1);
                }
            }
        }
        CP_WAIT1();
        __syncthreads();
        cur = (cur + 1) % 3;
    }

    // ---- epilogue: direct float2 stores ----
    const int crow = m0 + wm * 64 + (lane >> 2);
    const int ccol = n0 + wn * 32 + (lane & 3) * 2;
#pragma unroll
    for (int mt = 0; mt < 4; ++mt) {
#pragma unroll
        for (int nt = 0; nt < 4; ++nt) {
            float* cp = C + (size_t)(crow + mt * 16) * ldc + ccol + nt * 8;
            *(float2*)cp = make_float2(acc[mt][nt][0], acc[mt][nt][1]);
            *(float2*)(cp + (size_t)8 * ldc) = make_float2(acc[mt][nt][2], acc[mt][nt][3]);
        }
    }
}

// ---------------- launch ----------------
extern "C" void kernel_launch(void* const* d_in, const int* in_sizes, int n_in,
                              void* d_out, int out_size) {
    const float* x    = (const float*)d_in[0];
    const float* gw   = (const float*)d_in[1];
    const float* gb   = (const float*)d_in[2];
    const float* wgu  = (const float*)d_in[3];   // [E, D, 2I]
    const float* wdn  = (const float*)d_in[4];   // [E, I, D]
    const float* wsgu = (const float*)d_in[5];   // [D, 2*SI]
    const float* wsd  = (const float*)d_in[6];   // [SI, D]
    float* out = (float*)d_out;

    void* p;
    cudaGetSymbolAddress(&p, d_gu);      float* gu   = (float*)p;
    cudaGetSymbolAddress(&p, d_tok);     int*   tok  = (int*)p;
    cudaGetSymbolAddress(&p, d_counts);  int*   cnt  = (int*)p;
    cudaGetSymbolAddress(&p, d_top_idx); int*   ti   = (int*)p;
    cudaGetSymbolAddress(&p, d_top_w);   float* tw   = (float*)p;
    cudaGetSymbolAddress(&p, d_pos);     int*   pos  = (int*)p;
    cudaGetSymbolAddress(&p, d_xt);      float* xt   = (float*)p;
    cudaGetSymbolAddress(&p, d_wgu_t);   float* wguT = (float*)p;
    cudaGetSymbolAddress(&p, d_wdn_t);   float* wdnT = (float*)p;
    cudaGetSymbolAddress(&p, d_wsgu_t);  float* wsguT= (float*)p;
    cudaGetSymbolAddress(&p, d_wsd_t);   float* wsdT = (float*)p;
    cudaGetSymbolAddress(&p, d_acts);    float* acts = (float*)p;
    cudaGetSymbolAddress(&p, d_acte);    float* acte = (float*)p;

    cudaFuncSetAttribute(mma_gemm<false>, cudaFuncAttributeMaxDynamicSharedMemorySize, GSMEM_BYTES);
    cudaFuncSetAttribute(mma_gemm<true>,  cudaFuncAttributeMaxDynamicSharedMemorySize, GSMEM_BYTES);

    // --- prep: tf32 rounding + weight transposes to [N][K] ---
    round_x_kernel<<<(T_TOK * DIM / 4) / 256, 256>>>(x, xt);
    transpose_tf32<<<dim3((2 * NI) / 32, DIM / 32, NE), dim3(32, 8)>>>(
        wgu, (long long)DIM * 2 * NI, wguT, (long long)(2 * NI) * DIM, DIM, 2 * NI);
    transpose_tf32<<<dim3(DIM / 32, NI / 32, NE), dim3(32, 8)>>>(
        wdn, (long long)NI * DIM, wdnT, (long long)DIM * NI, NI, DIM);
    transpose_tf32<<<dim3((2 * SIH) / 32, DIM / 32, 1), dim3(32, 8)>>>(
        wsgu, 0, wsguT, 0, DIM, 2 * SIH);
    transpose_tf32<<<dim3(DIM / 32, SIH / 32, 1), dim3(32, 8)>>>(
        wsd, 0, wsdT, 0, SIH, DIM);

    // --- router + routing tables ---
    router_kernel<<<T_TOK, 128>>>(x, gw, gb, ti, tw);
    routing_build<<<NE, 256>>>(ti, tok, pos, cnt);

    // --- shared expert: gu = x @ wsgu  [2048 x 4096] ---
    mma_gemm<false><<<dim3((2 * SIH) / 128, T_TOK / 128, 1), 256, GSMEM_BYTES>>>(
        xt, 0, DIM, wsguT, 0, DIM, gu, 0, 2 * SIH,
        (const int*)0, T_TOK, DIM / 32, (const int*)0);
    swiglu_shared<<<(T_TOK * SIH / 4) / 256, 256>>>(gu, acts);
    // out = act @ wsd  [2048 x 2048] (full store initializes out)
    mma_gemm<false><<<dim3(DIM / 128, T_TOK / 128, 1), 256, GSMEM_BYTES>>>(
        acts, 0, SIH, wsdT, 0, SIH, out, 0, DIM,
        (const int*)0, T_TOK, SIH / 32, (const int*)0);

    // --- routed experts ---
    mma_gemm<true><<<dim3((2 * NI) / 128, CAP / 128, NE), 256, GSMEM_BYTES>>>(
        xt, 0, DIM, wguT, (long long)(2 * NI) * DIM, DIM,
        gu, (long long)CAP * (2 * NI), 2 * NI,
        cnt, 0, DIM / 32, tok);
    swiglu_expert<<<((size_t)NE * CAP * NI / 4) / 256, 256>>>(gu, acte, cnt);
    // y[e] = act[e] @ wdn[e]  (dense store into gu scratch reused as y)
    mma_gemm<false><<<dim3(DIM / 128, CAP / 128, NE), 256, GSMEM_BYTES>>>(
        acte, (long long)CAP * NI, NI, wdnT, (long long)DIM * NI, NI,
        gu, (long long)CAP * DIM, DIM,
        cnt, 0, NI / 32, (const int*)0);
    combine_kernel<<<T_TOK * 2, 256>>>(gu, ti, pos, tw, out);
}